// round 4
// baseline (speedup 1.0000x reference)
#include <cuda_runtime.h>

#define T_LEN 512
#define HH    50
#define G4    200      // 4*H gates
#define GB    16       // batch rows per CTA
#define NTHR  256
#define NCTA  128      // 2048 / GB

// shared layout (float offsets)
#define OFF_W0T   0        // [50][200]  Whh0^T
#define OFF_WCT   10000    // [100][200] [Wih1;Whh1]^T
#define OFF_WIH0  30000    // [200]
#define OFF_B0    30200    // [200]
#define OFF_B1    30400    // [200]
#define OFF_HCAT  30600    // [100][17]  rows 0..49 = h1, 50..99 = h2
#define OFF_C1    32300    // [50][17]
#define OFF_C2    33150    // [50][17]
#define OFF_GBUF  34000    // [200][17]
#define OFF_XS    37400    // [512][16]
#define SMEM_FLOATS 45592
#define SMEM_BYTES  (SMEM_FLOATS * 4)

__device__ __forceinline__ float sigf(float x) {
    return __fdividef(1.f, 1.f + __expf(-x));
}
__device__ __forceinline__ float tanh_fast(float x) {
    return fmaf(2.f, __fdividef(1.f, 1.f + __expf(-2.f * x)), -1.f);
}
__device__ __forceinline__ float4 fma4(float4 w, float h, float4 a) {
    a.x = fmaf(w.x, h, a.x);
    a.y = fmaf(w.y, h, a.y);
    a.z = fmaf(w.z, h, a.z);
    a.w = fmaf(w.w, h, a.w);
    return a;
}

extern __shared__ float sm[];

__global__ __launch_bounds__(NTHR, 1)
void lstm2_kernel(const float* __restrict__ x,
                  const float* __restrict__ Wih0, const float* __restrict__ Whh0,
                  const float* __restrict__ bih0, const float* __restrict__ bhh0,
                  const float* __restrict__ Wih1, const float* __restrict__ Whh1,
                  const float* __restrict__ bih1, const float* __restrict__ bhh1,
                  const float* __restrict__ Wfc,  const float* __restrict__ bfc,
                  float* __restrict__ out)
{
    float* W0T  = sm + OFF_W0T;
    float* WcT  = sm + OFF_WCT;
    float* wih0 = sm + OFF_WIH0;
    float* bias0 = sm + OFF_B0;
    float* bias1 = sm + OFF_B1;
    float* hcat = sm + OFF_HCAT;
    float* c1s  = sm + OFF_C1;
    float* c2s  = sm + OFF_C2;
    float* gbuf = sm + OFF_GBUF;
    float* xs   = sm + OFF_XS;

    const int tid = threadIdx.x;
    const int b0  = blockIdx.x * GB;

    // ---- stage weights (transposed: gate index j contiguous) ----
    for (int i = tid; i < G4 * HH; i += NTHR) {
        int j = i / HH, k = i % HH;
        W0T[k * G4 + j]        = Whh0[i];
        WcT[k * G4 + j]        = Wih1[i];
        WcT[(HH + k) * G4 + j] = Whh1[i];
    }
    for (int i = tid; i < G4; i += NTHR) {
        wih0[i]  = Wih0[i];
        bias0[i] = bih0[i] + bhh0[i];
        bias1[i] = bih1[i] + bhh1[i];
    }
    for (int i = tid; i < 100 * 17; i += NTHR) hcat[i] = 0.f;
    for (int i = tid; i < 50 * 17; i += NTHR) { c1s[i] = 0.f; c2s[i] = 0.f; }
    // stage x: xs[t*16 + b]
    for (int i = tid; i < GB * T_LEN; i += NTHR) {
        int t = i >> 4, b = i & 15;
        xs[i] = x[(b0 + b) * T_LEN + t];
    }
    __syncthreads();

    const int  s    = tid >> 4;       // gate slice 0..15
    const int  b    = tid & 15;       // batch row within CTA
    const bool has3 = (s < 2);        // chunks 48,49 handled by s=0,1
    const int  ch0 = s, ch1 = s + 16, ch2 = s + 32, ch3 = s + 48;

    const float4* W0T4  = (const float4*)W0T;    // rows of 50 float4
    const float4* WcT4  = (const float4*)WcT;
    const float4* b04   = (const float4*)bias0;
    const float4* b14   = (const float4*)bias1;
    const float4* wih04 = (const float4*)wih0;

    auto st_gates = [&](int c, float4 v) {
        int j = 4 * c;
        gbuf[(j + 0) * 17 + b] = v.x;
        gbuf[(j + 1) * 17 + b] = v.y;
        gbuf[(j + 2) * 17 + b] = v.z;
        gbuf[(j + 3) * 17 + b] = v.w;
    };

    for (int t = 0; t < T_LEN; ++t) {
        // ================= layer 0 gates =================
        float xv = xs[t * GB + b];
        float4 a0 = fma4(wih04[ch0], xv, b04[ch0]);
        float4 a1 = fma4(wih04[ch1], xv, b04[ch1]);
        float4 a2 = fma4(wih04[ch2], xv, b04[ch2]);
        float4 a3 = has3 ? fma4(wih04[ch3], xv, b04[ch3]) : make_float4(0.f, 0.f, 0.f, 0.f);

        #pragma unroll 5
        for (int k = 0; k < HH; ++k) {
            float hk = hcat[k * 17 + b];
            const float4* row = W0T4 + k * 50;
            a0 = fma4(row[ch0], hk, a0);
            a1 = fma4(row[ch1], hk, a1);
            a2 = fma4(row[ch2], hk, a2);
            if (has3) a3 = fma4(row[ch3], hk, a3);
        }
        st_gates(ch0, a0); st_gates(ch1, a1); st_gates(ch2, a2);
        if (has3) st_gates(ch3, a3);
        __syncthreads();

        // ================= layer 0 elementwise =================
        for (int i = tid; i < HH * GB; i += NTHR) {
            int k = i >> 4, bb = i & 15;
            float ig = sigf(gbuf[k * 17 + bb]);
            float fg = sigf(gbuf[(HH + k) * 17 + bb]);
            float gg = tanh_fast(gbuf[(2 * HH + k) * 17 + bb]);
            float og = sigf(gbuf[(3 * HH + k) * 17 + bb]);
            float c  = fmaf(fg, c1s[k * 17 + bb], ig * gg);
            c1s[k * 17 + bb]  = c;
            hcat[k * 17 + bb] = og * tanh_fast(c);
        }
        __syncthreads();

        // ================= layer 1 gates (input+recurrent fused) =================
        a0 = b14[ch0]; a1 = b14[ch1]; a2 = b14[ch2];
        a3 = has3 ? b14[ch3] : make_float4(0.f, 0.f, 0.f, 0.f);

        #pragma unroll 5
        for (int k = 0; k < 2 * HH; ++k) {
            float hk = hcat[k * 17 + b];
            const float4* row = WcT4 + k * 50;
            a0 = fma4(row[ch0], hk, a0);
            a1 = fma4(row[ch1], hk, a1);
            a2 = fma4(row[ch2], hk, a2);
            if (has3) a3 = fma4(row[ch3], hk, a3);
        }
        st_gates(ch0, a0); st_gates(ch1, a1); st_gates(ch2, a2);
        if (has3) st_gates(ch3, a3);
        __syncthreads();

        // ================= layer 1 elementwise =================
        for (int i = tid; i < HH * GB; i += NTHR) {
            int k = i >> 4, bb = i & 15;
            float ig = sigf(gbuf[k * 17 + bb]);
            float fg = sigf(gbuf[(HH + k) * 17 + bb]);
            float gg = tanh_fast(gbuf[(2 * HH + k) * 17 + bb]);
            float og = sigf(gbuf[(3 * HH + k) * 17 + bb]);
            float c  = fmaf(fg, c2s[k * 17 + bb], ig * gg);
            c2s[k * 17 + bb]        = c;
            hcat[(HH + k) * 17 + bb] = og * tanh_fast(c);
        }
        __syncthreads();
    }

    // ================= final classifier on h2[T-1] =================
    if (tid < GB * 2) {
        int bb = tid >> 1, cls = tid & 1;
        float acc = bfc[cls];
        #pragma unroll
        for (int k = 0; k < HH; ++k)
            acc = fmaf(Wfc[cls * HH + k], hcat[(HH + k) * 17 + bb], acc);
        out[(b0 + bb) * 2 + cls] = acc;
    }
}

extern "C" void kernel_launch(void* const* d_in, const int* in_sizes, int n_in,
                              void* d_out, int out_size)
{
    const float* x    = (const float*)d_in[0];
    const float* Wih0 = (const float*)d_in[1];
    const float* Whh0 = (const float*)d_in[2];
    const float* bih0 = (const float*)d_in[3];
    const float* bhh0 = (const float*)d_in[4];
    const float* Wih1 = (const float*)d_in[5];
    const float* Whh1 = (const float*)d_in[6];
    const float* bih1 = (const float*)d_in[7];
    const float* bhh1 = (const float*)d_in[8];
    const float* Wfc  = (const float*)d_in[9];
    const float* bfc  = (const float*)d_in[10];
    float* out = (float*)d_out;

    cudaFuncSetAttribute(lstm2_kernel,
                         cudaFuncAttributeMaxDynamicSharedMemorySize, SMEM_BYTES);
    lstm2_kernel<<<NCTA, NTHR, SMEM_BYTES>>>(
        x, Wih0, Whh0, bih0, bhh0, Wih1, Whh1, bih1, bhh1, Wfc, bfc, out);
}